// round 10
// baseline (speedup 1.0000x reference)
#include <cuda_runtime.h>
#include <cuda_bf16.h>
#include <cuda_fp8.h>
#include <math.h>
#include <stdint.h>

#define N_TOK   32768
#define N_CODE  8192
#define CDIM    256
#define HW      32

#define OUT_LOSS  8388608
#define OUT_PERP  8388609
#define OUT_IDX   8388610
#define OUT_TOTAL (8388608 + 2 + 32768)

#define CAP    48
#define EPS_S  12.0f      // in the x8192-scaled fp8 score domain (~1.46e-3 unscaled)

// ---------------- device scratch (no allocation allowed) ----------------
__device__ float    g_zflat[N_TOK * CDIM];     // fp32 [token][c]
__device__ uint8_t  g_z8[N_TOK * CDIM];        // fp8 e4m3 tokens
__device__ uint8_t  g_e8[N_CODE * CDIM];       // fp8 e4m3 codebook, scaled x8192
__device__ float    g_sumz[N_TOK];
__device__ float    g_sume[N_CODE];
__device__ float    g_sume_s[N_CODE];          // 8192 * sume
__device__ int      g_idx[N_TOK];
__device__ int      g_counts[N_CODE];
__device__ int      g_cand[N_TOK][CAP];
__device__ int      g_cnt[N_TOK];
__device__ double   g_mse;

// ---------------- baseline-PTX helpers ----------------
__device__ __forceinline__ uint32_t smem_u32(const void* p) {
    uint32_t a;
    asm("{ .reg .u64 t; cvta.to.shared.u64 t, %1; cvt.u32.u64 %0, t; }" : "=r"(a) : "l"(p));
    return a;
}
#define CP_ASYNC(dst, src) asm volatile("cp.async.cg.shared.global [%0], [%1], 16;" :: "r"(dst), "l"(src))
#define CP_COMMIT()        asm volatile("cp.async.commit_group;" ::: "memory")
#define CP_WAIT1()         asm volatile("cp.async.wait_group 1;" ::: "memory")
#define CP_WAIT0()         asm volatile("cp.async.wait_group 0;" ::: "memory")

#define LDSM4(r, addr) \
    asm volatile("ldmatrix.sync.aligned.m8n8.x4.shared.b16 {%0,%1,%2,%3}, [%4];" \
        : "=r"((r)[0]), "=r"((r)[1]), "=r"((r)[2]), "=r"((r)[3]) : "r"(addr))

#define MMA_FP8(d, a, b0, b1) \
    asm volatile("mma.sync.aligned.m16n8k32.row.col.f32.e4m3.e4m3.f32 " \
        "{%0,%1,%2,%3}, {%4,%5,%6,%7}, {%8,%9}, {%0,%1,%2,%3};" \
        : "+f"((d)[0]), "+f"((d)[1]), "+f"((d)[2]), "+f"((d)[3]) \
        : "r"((a)[0]), "r"((a)[1]), "r"((a)[2]), "r"((a)[3]), "r"(b0), "r"(b1))

__device__ __forceinline__ uint8_t to_fp8(float f) {
    __nv_fp8_storage_t s = __nv_cvt_float_to_fp8(f, __NV_SATFINITE, __NV_E4M3);
    return (uint8_t)s;
}

// ============================================================
// K0: fp8 codebook (x8192) + ||e||^2 + scaled sume + zero counts
// ============================================================
__global__ void k_prep(const float* __restrict__ emb) {
    int wid = threadIdx.x >> 5, lane = threadIdx.x & 31;
    int j = blockIdx.x * 8 + wid;
    if (blockIdx.x == 0 && threadIdx.x == 0) g_mse = 0.0;
    if (threadIdx.x < 8) g_counts[blockIdx.x * 8 + threadIdx.x] = 0;

    const float* r = emb + (size_t)j * CDIM + lane * 8;
    float4 v0 = *(const float4*)r;
    float4 v1 = *(const float4*)(r + 4);
    double s = (double)v0.x * v0.x + (double)v0.y * v0.y +
               (double)v0.z * v0.z + (double)v0.w * v0.w +
               (double)v1.x * v1.x + (double)v1.y * v1.y +
               (double)v1.z * v1.z + (double)v1.w * v1.w;
    #pragma unroll
    for (int off = 16; off; off >>= 1) s += __shfl_down_sync(0xffffffffu, s, off);
    if (lane == 0) {
        float se = (float)s;
        g_sume[j] = se;
        g_sume_s[j] = 8192.0f * se;
    }

    uint8_t b[8];
    b[0] = to_fp8(v0.x * 8192.0f); b[1] = to_fp8(v0.y * 8192.0f);
    b[2] = to_fp8(v0.z * 8192.0f); b[3] = to_fp8(v0.w * 8192.0f);
    b[4] = to_fp8(v1.x * 8192.0f); b[5] = to_fp8(v1.y * 8192.0f);
    b[6] = to_fp8(v1.z * 8192.0f); b[7] = to_fp8(v1.w * 8192.0f);
    *(uint2*)(g_e8 + (size_t)j * CDIM + lane * 8) = *(uint2*)b;
}

// ============================================================
// K1: transpose z -> z_flat (fp32 + fp8) + sumz + zero g_cnt
// ============================================================
__global__ void k_transpose(const float* __restrict__ z) {
    __shared__ float  tile[32][257];
    __shared__ double red[8][32];
    int bh = blockIdx.x;
    int b = bh >> 5, h = bh & 31;
    int tid = threadIdx.x;
    int w = tid & 31, c0 = tid >> 5;

    const float* zb = z + ((size_t)b * CDIM * HW + h) * HW;
    double pd = 0.0;
    #pragma unroll 4
    for (int cc = 0; cc < 32; cc++) {
        int c = c0 * 32 + cc;
        float v = zb[(size_t)c * 1024 + w];
        tile[w][c] = v;
        pd += (double)v * (double)v;
    }
    red[c0][w] = pd;
    __syncthreads();

    int base = bh * 32;
    if (tid < 32) {
        double s = 0.0;
        #pragma unroll
        for (int g = 0; g < 8; g++) s += red[g][tid];
        g_sumz[base + tid] = (float)s;
        g_cnt[base + tid] = 0;
    }
    #pragma unroll 4
    for (int w2 = 0; w2 < 32; w2++) {
        float v = tile[w2][tid];
        size_t o = (size_t)(base + w2) * CDIM + tid;
        g_zflat[o] = v;
        g_z8[o]    = to_fp8(v);
    }
}

// ============================================================
// Pass A: fp8 mma.sync GEMM + streaming min + candidate capture
// grid 512: CTA = 128 tokens x 4096 codes (split-J 2 halves, 32 tiles)
// 512 threads, 16 warps 4(m)x4(n), warp tile 32x32, m16n8k32 e4m3
// ============================================================
#define SM_A      0
#define SM_B0     32768
#define SM_B1     65536
#define SM_TOTAL  98304
#define NTHREADS  512

__device__ __forceinline__ void load_B_tile(int jt, uint32_t base, int tid) {
    const uint8_t* ep = g_e8 + (size_t)jt * 128 * CDIM;
    #pragma unroll
    for (int it = 0; it < 4; it++) {
        int idx = tid + it * NTHREADS;
        int r = idx >> 4, c = idx & 15;
        uint32_t dst = base + (uint32_t)r * 256u + (uint32_t)((c ^ (r & 7)) * 16);
        CP_ASYNC(dst, (const void*)(ep + (size_t)r * CDIM + c * 16));
    }
}

#define LOAD_FRAGS(slot, kss) do {                                                   \
    uint32_t _ad0 = a_row[0] + (uint32_t)(((((kss) * 2 + a_hi)) ^ a_rl[0]) * 16);    \
    LDSM4(af[slot][0], _ad0);                                                        \
    uint32_t _ad1 = a_row[1] + (uint32_t)(((((kss) * 2 + a_hi)) ^ a_rl[1]) * 16);    \
    LDSM4(af[slot][1], _ad1);                                                        \
    uint32_t _bd0 = bbuf + (uint32_t)b_rowoff[0] + (uint32_t)(((((kss) * 2 + b_hi)) ^ b_rl[0]) * 16); \
    LDSM4(bf[slot][0], _bd0);                                                        \
    uint32_t _bd1 = bbuf + (uint32_t)b_rowoff[1] + (uint32_t)(((((kss) * 2 + b_hi)) ^ b_rl[1]) * 16); \
    LDSM4(bf[slot][1], _bd1);                                                        \
} while (0)

__global__ void __launch_bounds__(NTHREADS, 1) k_passA() {
    extern __shared__ char smem[];
    const uint32_t sb = smem_u32(smem);
    int tid = threadIdx.x, lane = tid & 31, wid = tid >> 5;
    int warp_m = wid >> 2, warp_n = wid & 3;
    int m0 = (blockIdx.x >> 1) * 128;
    int half = blockIdx.x & 1;

    // stage A tile (128 tokens x 256 fp8 = 32KB) into swizzled SMEM
    {
        const uint8_t* za = g_z8 + (size_t)m0 * CDIM;
        #pragma unroll
        for (int it = 0; it < 4; it++) {
            int idx = tid + it * NTHREADS;
            int r = idx >> 4, c = idx & 15;
            uint32_t dst = sb + SM_A + (uint32_t)r * 256u + (uint32_t)((c ^ (r & 7)) * 16);
            CP_ASYNC(dst, (const void*)(za + (size_t)r * CDIM + c * 16));
        }
    }
    CP_COMMIT();
    load_B_tile(half * 32, sb + SM_B0, tid);
    CP_COMMIT();

    uint32_t a_row[2]; int a_rl[2];
    #pragma unroll
    for (int mi = 0; mi < 2; mi++) {
        int row = warp_m * 32 + mi * 16 + (lane & 15);
        a_row[mi] = sb + SM_A + (uint32_t)row * 256u;
        a_rl[mi] = row & 7;
    }
    int a_hi = (lane >> 4) & 1;
    int q = lane >> 3;
    int b_hi = q & 1;
    int b_rowoff[2]; int b_rl[2];
    #pragma unroll
    for (int p = 0; p < 2; p++) {
        int row = warp_n * 32 + p * 16 + ((q & 2) << 2) + (lane & 7);
        b_rowoff[p] = row * 256;
        b_rl[p] = row & 7;
    }

    float bd[4];
    #pragma unroll
    for (int i = 0; i < 4; i++) bd[i] = 3.4e38f;

    for (int t = 0; t < 32; t++) {
        int jt = half * 32 + t;
        uint32_t bbuf = sb + ((t & 1) ? SM_B1 : SM_B0);
        if (t + 1 < 32) {
            load_B_tile(jt + 1, sb + ((t & 1) ? SM_B0 : SM_B1), tid);
            CP_COMMIT();
            CP_WAIT1();
        } else {
            CP_WAIT0();
        }
        __syncthreads();

        float acc[2][4][4];
        #pragma unroll
        for (int mi = 0; mi < 2; mi++)
            #pragma unroll
            for (int ni = 0; ni < 4; ni++)
                #pragma unroll
                for (int e = 0; e < 4; e++) acc[mi][ni][e] = 0.0f;

        // software-pipelined k-loop: 8 ksteps of k32
        uint32_t af[2][2][4], bf[2][2][4];
        LOAD_FRAGS(0, 0);
        #pragma unroll
        for (int ks = 0; ks < 8; ks++) {
            int cur = ks & 1, nxt = cur ^ 1;
            if (ks < 7) LOAD_FRAGS(nxt, ks + 1);
            #pragma unroll
            for (int mi = 0; mi < 2; mi++) {
                MMA_FP8(acc[mi][0], af[cur][mi], bf[cur][0][0], bf[cur][0][1]);
                MMA_FP8(acc[mi][1], af[cur][mi], bf[cur][0][2], bf[cur][0][3]);
                MMA_FP8(acc[mi][2], af[cur][mi], bf[cur][1][0], bf[cur][1][1]);
                MMA_FP8(acc[mi][3], af[cur][mi], bf[cur][1][2], bf[cur][1][3]);
            }
        }

        // ---- epilogue: scaled scores, running min, candidate capture ----
        float se[4][2];
        int colbase = jt * 128 + warp_n * 32 + 2 * (lane & 3);
        #pragma unroll
        for (int ni = 0; ni < 4; ni++) {
            se[ni][0] = __ldg(&g_sume_s[colbase + ni * 8]);
            se[ni][1] = __ldg(&g_sume_s[colbase + ni * 8 + 1]);
        }
        #pragma unroll
        for (int mi = 0; mi < 2; mi++) {
            #pragma unroll
            for (int hf = 0; hf < 2; hf++) {
                float s[8];
                #pragma unroll
                for (int ni = 0; ni < 4; ni++) {
                    s[ni * 2 + 0] = fmaf(-2.0f, acc[mi][ni][hf * 2 + 0], se[ni][0]);
                    s[ni * 2 + 1] = fmaf(-2.0f, acc[mi][ni][hf * 2 + 1], se[ni][1]);
                }
                float lmin = s[0];
                #pragma unroll
                for (int v = 1; v < 8; v++) lmin = fminf(lmin, s[v]);
                lmin = fminf(lmin, __shfl_xor_sync(0xffffffffu, lmin, 1));
                lmin = fminf(lmin, __shfl_xor_sync(0xffffffffu, lmin, 2));
                int bi = mi * 2 + hf;
                float nm = fminf(bd[bi], lmin);
                if (lmin < bd[bi] + EPS_S) {
                    int n = m0 + warp_m * 32 + mi * 16 + hf * 8 + (lane >> 2);
                    #pragma unroll
                    for (int v = 0; v < 8; v++) {
                        if (s[v] < nm + EPS_S) {
                            int pos = atomicAdd(&g_cnt[n], 1);
                            if (pos < CAP)
                                g_cand[n][pos] = colbase + (v >> 1) * 8 + (v & 1);
                        }
                    }
                }
                bd[bi] = nm;
            }
        }
        __syncthreads();
    }
}

// ============================================================
// Pass B v2: exact fp32 (reference-rounded) re-argmin
// block = 32 tokens; coalesced SMEM staging; packed atomicMin
// ============================================================
#define PB_TOK  32
#define PB_WAVE 128
// dyn smem: zrow 32*257f | crow 128*257f | res 32ull | Ssh 32f | list 1536i | ofl 32i
#define PB_SMEM (32*257*4 + 128*257*4 + 32*8 + 32*4 + 32*CAP*4 + 32*4)

__global__ void __launch_bounds__(256) k_passB(const float* __restrict__ emb,
                                               float* __restrict__ out_idx, int write_idx) {
    extern __shared__ char pbs[];
    float* zrow = (float*)pbs;                                  // [32][257]
    float* crow = zrow + 32 * 257;                              // [128][257]
    unsigned long long* res = (unsigned long long*)(crow + 128 * 257);
    float* Ssh = (float*)(res + 32);
    int* list = (int*)(Ssh + 32);                               // (tok<<13)|j
    int* ofl  = list + 32 * CAP;
    __shared__ int Tsh;

    int tid = threadIdx.x, lane = tid & 31, wid = tid >> 5;
    int base = blockIdx.x * PB_TOK;

    // stage z rows (scalar stores into 257-padded rows)
    for (int i = tid; i < PB_TOK * 64; i += 256) {
        int r = i >> 6, c4 = i & 63;
        float4 v = *(const float4*)(g_zflat + (size_t)(base + r) * CDIM + c4 * 4);
        float* dst = &zrow[r * 257 + c4 * 4];
        dst[0] = v.x; dst[1] = v.y; dst[2] = v.z; dst[3] = v.w;
    }
    if (tid < 32) {
        Ssh[tid] = g_sumz[base + tid];
        res[tid] = ~0ull;
    }
    // build compact candidate list (warp 0)
    if (tid < 32) {
        int n = base + tid;
        int cnt = g_cnt[n];
        int ok = (cnt <= CAP);
        ofl[tid] = !ok;
        int c2 = ok ? cnt : 0;
        int off = c2;
        #pragma unroll
        for (int d = 1; d < 32; d <<= 1) {
            int v = __shfl_up_sync(0xffffffffu, off, d);
            if (lane >= d) off += v;
        }
        int start = off - c2;
        for (int c = 0; c < c2; c++) list[start + c] = (tid << 13) | g_cand[n][c];
        if (tid == 31) Tsh = off;
    }
    __syncthreads();

    int T = Tsh;
    for (int w = 0; w < T; w += PB_WAVE) {
        int nr = min(PB_WAVE, T - w);
        // coalesced stage of candidate rows
        for (int i = tid; i < nr * 64; i += 256) {
            int r = i >> 6, c4 = i & 63;
            int j = list[w + r] & 8191;
            float4 v = *(const float4*)(emb + (size_t)j * CDIM + c4 * 4);
            float* dst = &crow[r * 257 + c4 * 4];
            dst[0] = v.x; dst[1] = v.y; dst[2] = v.z; dst[3] = v.w;
        }
        __syncthreads();
        if (tid < nr) {
            int e = list[w + tid];
            int tok = e >> 13, j = e & 8191;
            const float* zr = &zrow[tok * 257];
            const float* cr = &crow[tid * 257];
            float g = 0.0f;
            #pragma unroll 8
            for (int k = 0; k < CDIM; k++) g = fmaf(zr[k], cr[k], g);
            float d = __fadd_rn(fmaf(-2.0f, g, Ssh[tok]), __ldg(&g_sume[j]));
            unsigned u = __float_as_uint(d);
            unsigned key = (u & 0x80000000u) ? ~u : (u | 0x80000000u);
            atomicMin(&res[tok], ((unsigned long long)key << 32) | (unsigned)j);
        }
        __syncthreads();
    }

    // rare fallback: full exact scan for overflowed tokens (one warp each)
    for (int t2 = wid; t2 < 32; t2 += 8) {
        if (!ofl[t2]) continue;
        const float* zr = &zrow[t2 * 257];
        float S = Ssh[t2];
        unsigned long long best = ~0ull;
        for (int j = lane; j < N_CODE; j += 32) {
            const float* ep = emb + (size_t)j * CDIM;
            float g = 0.0f;
            for (int k = 0; k < CDIM; k++) g = fmaf(zr[k], __ldg(&ep[k]), g);
            float d = __fadd_rn(fmaf(-2.0f, g, S), __ldg(&g_sume[j]));
            unsigned u = __float_as_uint(d);
            unsigned key = (u & 0x80000000u) ? ~u : (u | 0x80000000u);
            unsigned long long pk = ((unsigned long long)key << 32) | (unsigned)j;
            if (pk < best) best = pk;
        }
        #pragma unroll
        for (int off = 16; off; off >>= 1) {
            unsigned long long o = __shfl_down_sync(0xffffffffu, best, off);
            if (o < best) best = o;
        }
        if (lane == 0) atomicMin(&res[t2], best);
    }
    __syncthreads();

    if (tid < 32) {
        unsigned long long rv = res[tid];
        int j = (int)(rv & 0xFFFFFFFFull);
        int n = base + tid;
        g_idx[n] = j;
        atomicAdd(&g_counts[j], 1);
        if (write_idx) out_idx[n] = (float)j;
    }
}

// ============================================================
// K3: gather z_q, write z_q_st in [b,c,h,w], mse
// ============================================================
__global__ void k_output(const float* __restrict__ z, const float* __restrict__ emb,
                         float* __restrict__ out) {
    __shared__ float  tile[32][257];
    __shared__ double red[256];
    int bh = blockIdx.x;
    int b = bh >> 5, h = bh & 31;
    int tid = threadIdx.x;
    int base = bh * 32;

    for (int w = 0; w < 32; w++) {
        int idx = g_idx[base + w];
        tile[w][tid] = emb[(size_t)idx * CDIM + tid];
    }
    __syncthreads();

    int w = tid & 31, c0 = tid >> 5;
    const float* zb = z   + ((size_t)b * CDIM * HW + h) * HW;
    float*       ob = out + ((size_t)b * CDIM * HW + h) * HW;
    double macc = 0.0;
    #pragma unroll 4
    for (int cc = 0; cc < 32; cc++) {
        int c = c0 * 32 + cc;
        size_t off = (size_t)c * 1024 + w;
        float zv = zb[off];
        float q  = tile[w][c];
        float diff = __fsub_rn(q, zv);
        ob[off] = __fadd_rn(zv, diff);
        double e = (double)zv - (double)q;
        macc += e * e;
    }
    red[tid] = macc;
    __syncthreads();
    #pragma unroll
    for (int s = 128; s; s >>= 1) {
        if (tid < s) red[tid] += red[tid + s];
        __syncthreads();
    }
    if (tid == 0) atomicAdd(&g_mse, red[0]);
}

// ============================================================
// K4: scalars
// ============================================================
__global__ void k_scalars(float* __restrict__ out_scalars) {
    __shared__ double red[256];
    int tid = threadIdx.x;
    double s = 0.0;
    for (int j = tid; j < N_CODE; j += 256) {
        int c = g_counts[j];
        if (c > 0) {
            double p = (double)c / (double)N_TOK;
            s += p * log(p);
        }
    }
    red[tid] = s;
    __syncthreads();
    #pragma unroll
    for (int st = 128; st; st >>= 1) {
        if (tid < st) red[tid] += red[tid + st];
        __syncthreads();
    }
    if (tid == 0) {
        double loss = 1.25 * g_mse / (double)((size_t)N_TOK * CDIM);
        out_scalars[0] = (float)loss;
        out_scalars[1] = (float)exp(-red[0]);
    }
}

// ============================================================
extern "C" void kernel_launch(void* const* d_in, const int* in_sizes, int n_in,
                              void* d_out, int out_size) {
    const float* z   = (const float*)d_in[0];
    const float* emb = (const float*)d_in[1];
    float* out = (float*)d_out;

    int has_extra = (out_size >= (int)OUT_TOTAL) ? 1 : 0;

    cudaFuncSetAttribute(k_passA, cudaFuncAttributeMaxDynamicSharedMemorySize, SM_TOTAL);
    cudaFuncSetAttribute(k_passB, cudaFuncAttributeMaxDynamicSharedMemorySize, PB_SMEM);

    k_prep<<<N_CODE / 8, 256>>>(emb);
    k_transpose<<<1024, 256>>>(z);
    k_passA<<<(N_TOK / 128) * 2, NTHREADS, SM_TOTAL>>>();
    k_passB<<<N_TOK / PB_TOK, 256, PB_SMEM>>>(emb, out + OUT_IDX, has_extra);
    k_output<<<1024, 256>>>(z, emb, out);
    if (has_extra) k_scalars<<<1, 256>>>(out + OUT_LOSS);
}

// round 12
// speedup vs baseline: 281.1393x; 281.1393x over previous
#include <cuda_runtime.h>
#include <cuda_bf16.h>
#include <math.h>
#include <stdint.h>

#define N_TOK   32768
#define N_CODE  8192
#define CDIM    256
#define HW      32

#define OUT_LOSS  8388608
#define OUT_PERP  8388609
#define OUT_IDX   8388610
#define OUT_TOTAL (8388608 + 2 + 32768)

#define CAP   48
#define EPS   7e-5f

// ---------------- device scratch (no allocation allowed) ----------------
__device__ float          g_zflat[N_TOK * CDIM];      // fp32 [token][c]
__device__ __nv_bfloat16  g_zf16[N_TOK * CDIM];       // bf16 tokens
__device__ __nv_bfloat16  g_ef16[N_CODE * CDIM];      // bf16 codebook
__device__ float          g_sumz[N_TOK];
__device__ float          g_sume[N_CODE];
__device__ int            g_idx[N_TOK];
__device__ int            g_counts[N_CODE];
__device__ int            g_cand[N_TOK][CAP];
__device__ int            g_cnt[N_TOK];
__device__ double         g_mse;

// ---------------- baseline-PTX helpers (NO sm_103a-only features) ----------------
__device__ __forceinline__ uint32_t smem_u32(const void* p) {
    uint32_t a;
    asm("{ .reg .u64 t; cvta.to.shared.u64 t, %1; cvt.u32.u64 %0, t; }" : "=r"(a) : "l"(p));
    return a;
}
#define CP_ASYNC(dst, src) asm volatile("cp.async.cg.shared.global [%0], [%1], 16;" :: "r"(dst), "l"(src))
#define CP_COMMIT()        asm volatile("cp.async.commit_group;" ::: "memory")
#define CP_WAIT1()         asm volatile("cp.async.wait_group 1;" ::: "memory")
#define CP_WAIT0()         asm volatile("cp.async.wait_group 0;" ::: "memory")

#define LDSM4(r, addr) \
    asm volatile("ldmatrix.sync.aligned.m8n8.x4.shared.b16 {%0,%1,%2,%3}, [%4];" \
        : "=r"((r)[0]), "=r"((r)[1]), "=r"((r)[2]), "=r"((r)[3]) : "r"(addr))

#define MMA_BF16(d, a, b0, b1) \
    asm volatile("mma.sync.aligned.m16n8k16.row.col.f32.bf16.bf16.f32 " \
        "{%0,%1,%2,%3}, {%4,%5,%6,%7}, {%8,%9}, {%0,%1,%2,%3};" \
        : "+f"((d)[0]), "+f"((d)[1]), "+f"((d)[2]), "+f"((d)[3]) \
        : "r"((a)[0]), "r"((a)[1]), "r"((a)[2]), "r"((a)[3]), "r"(b0), "r"(b1))

// ============================================================
// K0 (fused): bf16 codebook + ||e||^2 + zero counts/mse
// ============================================================
__global__ void k_prep(const float* __restrict__ emb) {
    int wid = threadIdx.x >> 5, lane = threadIdx.x & 31;
    int j = blockIdx.x * 8 + wid;
    if (blockIdx.x == 0 && threadIdx.x == 0) g_mse = 0.0;
    if (threadIdx.x < 8) g_counts[blockIdx.x * 8 + threadIdx.x] = 0;

    const float* r = emb + (size_t)j * CDIM + lane * 8;
    float4 v0 = *(const float4*)r;
    float4 v1 = *(const float4*)(r + 4);
    double s = (double)v0.x * v0.x + (double)v0.y * v0.y +
               (double)v0.z * v0.z + (double)v0.w * v0.w +
               (double)v1.x * v1.x + (double)v1.y * v1.y +
               (double)v1.z * v1.z + (double)v1.w * v1.w;
    #pragma unroll
    for (int off = 16; off; off >>= 1) s += __shfl_down_sync(0xffffffffu, s, off);
    if (lane == 0) g_sume[j] = (float)s;

    __nv_bfloat16 b[8];
    b[0] = __float2bfloat16(v0.x); b[1] = __float2bfloat16(v0.y);
    b[2] = __float2bfloat16(v0.z); b[3] = __float2bfloat16(v0.w);
    b[4] = __float2bfloat16(v1.x); b[5] = __float2bfloat16(v1.y);
    b[6] = __float2bfloat16(v1.z); b[7] = __float2bfloat16(v1.w);
    *(uint4*)(g_ef16 + (size_t)j * CDIM + lane * 8) = *(uint4*)b;
}

// ============================================================
// K1: transpose z -> z_flat (fp32 + bf16) + sumz
// ============================================================
__global__ void k_transpose(const float* __restrict__ z) {
    __shared__ float  tile[32][257];
    __shared__ double red[8][32];
    int bh = blockIdx.x;
    int b = bh >> 5, h = bh & 31;
    int tid = threadIdx.x;
    int w = tid & 31, c0 = tid >> 5;

    const float* zb = z + ((size_t)b * CDIM * HW + h) * HW;
    double pd = 0.0;
    #pragma unroll 4
    for (int cc = 0; cc < 32; cc++) {
        int c = c0 * 32 + cc;
        float v = zb[(size_t)c * 1024 + w];
        tile[w][c] = v;
        pd += (double)v * (double)v;
    }
    red[c0][w] = pd;
    __syncthreads();

    int base = bh * 32;
    if (tid < 32) {
        double s = 0.0;
        #pragma unroll
        for (int g = 0; g < 8; g++) s += red[g][tid];
        g_sumz[base + tid] = (float)s;
    }
    #pragma unroll 4
    for (int w2 = 0; w2 < 32; w2++) {
        float v = tile[w2][tid];
        size_t o = (size_t)(base + w2) * CDIM + tid;
        g_zflat[o] = v;
        g_zf16[o]  = __float2bfloat16(v);
    }
}

// ============================================================
// Pass A: bf16 mma.sync GEMM + streaming min + candidate capture
// CTA = 128 tokens x 8192 codes (64 tiles of 128 codes)
// 512 threads, 16 warps in 4(m) x 4(n), warp tile 32x32, m16n8k16
// k-loop fragments explicitly double-buffered (LDSM ks+1 || MMA ks)
// ============================================================
#define SM_A      0
#define SM_B0     65536
#define SM_B1     131072
#define SM_CNT    196608
#define SM_TOTAL  (196608 + 512)
#define NTHREADS  512

__device__ __forceinline__ void load_B_tile(int t, uint32_t base, int tid) {
    const __nv_bfloat16* ep = g_ef16 + (size_t)t * 128 * CDIM;
    #pragma unroll
    for (int it = 0; it < 8; it++) {
        int idx = tid + it * NTHREADS;
        int r = idx >> 5, c = idx & 31;
        uint32_t dst = base + (uint32_t)r * 512u + (uint32_t)((c ^ (r & 7)) * 16);
        CP_ASYNC(dst, (const void*)(ep + (size_t)r * CDIM + c * 8));
    }
}

#define LOAD_FRAGS(slot, kss) do {                                                   \
    uint32_t _ad0 = a_row[0] + (uint32_t)(((((kss) * 2 + a_hi)) ^ a_rl[0]) * 16);    \
    LDSM4(af[slot][0], _ad0);                                                        \
    uint32_t _ad1 = a_row[1] + (uint32_t)(((((kss) * 2 + a_hi)) ^ a_rl[1]) * 16);    \
    LDSM4(af[slot][1], _ad1);                                                        \
    uint32_t _bd0 = bbuf + (uint32_t)b_rowoff[0] + (uint32_t)(((((kss) * 2 + b_hi)) ^ b_rl[0]) * 16); \
    LDSM4(bf[slot][0], _bd0);                                                        \
    uint32_t _bd1 = bbuf + (uint32_t)b_rowoff[1] + (uint32_t)(((((kss) * 2 + b_hi)) ^ b_rl[1]) * 16); \
    LDSM4(bf[slot][1], _bd1);                                                        \
} while (0)

__global__ void __launch_bounds__(NTHREADS, 1) k_passA() {
    extern __shared__ char smem[];
    const uint32_t sb = smem_u32(smem);
    int* scnt = (int*)(smem + SM_CNT);
    int tid = threadIdx.x, lane = tid & 31, wid = tid >> 5;
    int warp_m = wid >> 2, warp_n = wid & 3;
    int m0 = blockIdx.x * 128;

    if (tid < 128) scnt[tid] = 0;

    // stage whole A tile (128 tokens x 256) into swizzled SMEM
    {
        const __nv_bfloat16* za = g_zf16 + (size_t)m0 * CDIM;
        #pragma unroll
        for (int it = 0; it < 8; it++) {
            int idx = tid + it * NTHREADS;
            int r = idx >> 5, c = idx & 31;
            uint32_t dst = sb + SM_A + (uint32_t)r * 512u + (uint32_t)((c ^ (r & 7)) * 16);
            CP_ASYNC(dst, (const void*)(za + (size_t)r * CDIM + c * 8));
        }
    }
    CP_COMMIT();
    load_B_tile(0, sb + SM_B0, tid);
    CP_COMMIT();

    uint32_t a_row[2]; int a_rl[2];
    #pragma unroll
    for (int mi = 0; mi < 2; mi++) {
        int row = warp_m * 32 + mi * 16 + (lane & 15);
        a_row[mi] = sb + SM_A + (uint32_t)row * 512u;
        a_rl[mi] = row & 7;
    }
    int a_hi = (lane >> 4) & 1;
    int q = lane >> 3;
    int b_hi = q & 1;
    int b_rowoff[2]; int b_rl[2];
    #pragma unroll
    for (int p = 0; p < 2; p++) {
        int row = warp_n * 32 + p * 16 + ((q & 2) << 2) + (lane & 7);
        b_rowoff[p] = row * 512;
        b_rl[p] = row & 7;
    }

    float bd[4];
    #pragma unroll
    for (int i = 0; i < 4; i++) bd[i] = 3.4e38f;

    for (int t = 0; t < 64; t++) {
        uint32_t bbuf = sb + ((t & 1) ? SM_B1 : SM_B0);
        if (t + 1 < 64) {
            load_B_tile(t + 1, sb + ((t & 1) ? SM_B0 : SM_B1), tid);
            CP_COMMIT();
            CP_WAIT1();
        } else {
            CP_WAIT0();
        }
        __syncthreads();

        float acc[2][4][4];
        #pragma unroll
        for (int mi = 0; mi < 2; mi++)
            #pragma unroll
            for (int ni = 0; ni < 4; ni++)
                #pragma unroll
                for (int e = 0; e < 4; e++) acc[mi][ni][e] = 0.0f;

        // software-pipelined k-loop: frags double-buffered in regs
        uint32_t af[2][2][4], bf[2][2][4];
        LOAD_FRAGS(0, 0);
        #pragma unroll
        for (int ks = 0; ks < 16; ks++) {
            int cur = ks & 1, nxt = cur ^ 1;
            if (ks < 15) LOAD_FRAGS(nxt, ks + 1);
            #pragma unroll
            for (int mi = 0; mi < 2; mi++) {
                MMA_BF16(acc[mi][0], af[cur][mi], bf[cur][0][0], bf[cur][0][1]);
                MMA_BF16(acc[mi][1], af[cur][mi], bf[cur][0][2], bf[cur][0][3]);
                MMA_BF16(acc[mi][2], af[cur][mi], bf[cur][1][0], bf[cur][1][1]);
                MMA_BF16(acc[mi][3], af[cur][mi], bf[cur][1][2], bf[cur][1][3]);
            }
        }

        // ---- epilogue: scores, running min, candidate capture ----
        float se[4][2];
        int colbase = t * 128 + warp_n * 32 + 2 * (lane & 3);
        #pragma unroll
        for (int ni = 0; ni < 4; ni++) {
            se[ni][0] = __ldg(&g_sume[colbase + ni * 8]);
            se[ni][1] = __ldg(&g_sume[colbase + ni * 8 + 1]);
        }
        #pragma unroll
        for (int mi = 0; mi < 2; mi++) {
            #pragma unroll
            for (int half = 0; half < 2; half++) {
                float s[8];
                #pragma unroll
                for (int ni = 0; ni < 4; ni++) {
                    s[ni * 2 + 0] = fmaf(-2.0f, acc[mi][ni][half * 2 + 0], se[ni][0]);
                    s[ni * 2 + 1] = fmaf(-2.0f, acc[mi][ni][half * 2 + 1], se[ni][1]);
                }
                float lmin = s[0];
                #pragma unroll
                for (int v = 1; v < 8; v++) lmin = fminf(lmin, s[v]);
                lmin = fminf(lmin, __shfl_xor_sync(0xffffffffu, lmin, 1));
                lmin = fminf(lmin, __shfl_xor_sync(0xffffffffu, lmin, 2));
                int bi = mi * 2 + half;
                float nm = fminf(bd[bi], lmin);
                if (lmin < bd[bi] + EPS) {
                    int r_local = warp_m * 32 + mi * 16 + half * 8 + (lane >> 2);
                    #pragma unroll
                    for (int v = 0; v < 8; v++) {
                        if (s[v] < nm + EPS) {
                            int pos = atomicAdd(&scnt[r_local], 1);
                            if (pos < CAP)
                                g_cand[m0 + r_local][pos] = colbase + (v >> 1) * 8 + (v & 1);
                        }
                    }
                }
                bd[bi] = nm;
            }
        }
        __syncthreads();
    }

    if (tid < 128) g_cnt[m0 + tid] = scnt[tid];
}

// ============================================================
// Pass B: exact fp32 (reference-rounded) re-argmin over candidates
// early-out: cnt==1 ==> the lone candidate IS the argmin (superset
// property: the running-min's own code is always captured)
// ============================================================
__global__ void __launch_bounds__(256) k_passB(const float* __restrict__ emb,
                                               float* __restrict__ out_idx, int write_idx) {
    __shared__ float zrow[8][CDIM];
    int wid = threadIdx.x >> 5, lane = threadIdx.x & 31;
    int n = blockIdx.x * 8 + wid;

    int cnt = g_cnt[n];
    if (cnt == 1) {
        if (lane == 0) {
            int j = g_cand[n][0];
            g_idx[n] = j;
            atomicAdd(&g_counts[j], 1);
            if (write_idx) out_idx[n] = (float)j;
        }
        return;
    }

    const float* zp = g_zflat + (size_t)n * CDIM;
    *(float4*)&zrow[wid][lane * 8]     = *(const float4*)(zp + lane * 8);
    *(float4*)&zrow[wid][lane * 8 + 4] = *(const float4*)(zp + lane * 8 + 4);
    __syncwarp();

    float S = g_sumz[n];
    float dbest = 3.4e38f;
    int jbest = 0x7fffffff;

    if (cnt <= CAP) {
        for (int ci = lane; ci < cnt; ci += 32) {
            int j = g_cand[n][ci];
            const float* ep = emb + (size_t)j * CDIM;
            float g = 0.0f;
            for (int k = 0; k < CDIM; k += 8) {
                float4 e0 = *(const float4*)(ep + k);
                float4 e1 = *(const float4*)(ep + k + 4);
                g = fmaf(zrow[wid][k + 0], e0.x, g);
                g = fmaf(zrow[wid][k + 1], e0.y, g);
                g = fmaf(zrow[wid][k + 2], e0.z, g);
                g = fmaf(zrow[wid][k + 3], e0.w, g);
                g = fmaf(zrow[wid][k + 4], e1.x, g);
                g = fmaf(zrow[wid][k + 5], e1.y, g);
                g = fmaf(zrow[wid][k + 6], e1.z, g);
                g = fmaf(zrow[wid][k + 7], e1.w, g);
            }
            float d = __fadd_rn(fmaf(-2.0f, g, S), g_sume[j]);
            if (d < dbest || (d == dbest && j < jbest)) { dbest = d; jbest = j; }
        }
    } else {
        for (int j = lane; j < N_CODE; j += 32) {
            const float* ep = emb + (size_t)j * CDIM;
            float g = 0.0f;
            for (int k = 0; k < CDIM; k += 8) {
                float4 e0 = *(const float4*)(ep + k);
                float4 e1 = *(const float4*)(ep + k + 4);
                g = fmaf(zrow[wid][k + 0], e0.x, g);
                g = fmaf(zrow[wid][k + 1], e0.y, g);
                g = fmaf(zrow[wid][k + 2], e0.z, g);
                g = fmaf(zrow[wid][k + 3], e0.w, g);
                g = fmaf(zrow[wid][k + 4], e1.x, g);
                g = fmaf(zrow[wid][k + 5], e1.y, g);
                g = fmaf(zrow[wid][k + 6], e1.z, g);
                g = fmaf(zrow[wid][k + 7], e1.w, g);
            }
            float d = __fadd_rn(fmaf(-2.0f, g, S), g_sume[j]);
            if (d < dbest || (d == dbest && j < jbest)) { dbest = d; jbest = j; }
        }
    }
    #pragma unroll
    for (int off = 16; off; off >>= 1) {
        float d2 = __shfl_down_sync(0xffffffffu, dbest, off);
        int   j2 = __shfl_down_sync(0xffffffffu, jbest, off);
        if (d2 < dbest || (d2 == dbest && j2 < jbest)) { dbest = d2; jbest = j2; }
    }
    if (lane == 0) {
        g_idx[n] = jbest;
        atomicAdd(&g_counts[jbest], 1);
        if (write_idx) out_idx[n] = (float)jbest;
    }
}

// ============================================================
// K3: gather z_q, write z_q_st in [b,c,h,w], mse
// ============================================================
__global__ void k_output(const float* __restrict__ z, const float* __restrict__ emb,
                         float* __restrict__ out) {
    __shared__ float  tile[32][257];
    __shared__ double red[256];
    int bh = blockIdx.x;
    int b = bh >> 5, h = bh & 31;
    int tid = threadIdx.x;
    int base = bh * 32;

    for (int w = 0; w < 32; w++) {
        int idx = g_idx[base + w];
        tile[w][tid] = emb[(size_t)idx * CDIM + tid];
    }
    __syncthreads();

    int w = tid & 31, c0 = tid >> 5;
    const float* zb = z   + ((size_t)b * CDIM * HW + h) * HW;
    float*       ob = out + ((size_t)b * CDIM * HW + h) * HW;
    double macc = 0.0;
    #pragma unroll 4
    for (int cc = 0; cc < 32; cc++) {
        int c = c0 * 32 + cc;
        size_t off = (size_t)c * 1024 + w;
        float zv = zb[off];
        float q  = tile[w][c];
        float diff = __fsub_rn(q, zv);
        ob[off] = __fadd_rn(zv, diff);
        double e = (double)zv - (double)q;
        macc += e * e;
    }
    red[tid] = macc;
    __syncthreads();
    #pragma unroll
    for (int s = 128; s; s >>= 1) {
        if (tid < s) red[tid] += red[tid + s];
        __syncthreads();
    }
    if (tid == 0) atomicAdd(&g_mse, red[0]);
}

// ============================================================
// K4: scalars
// ============================================================
__global__ void k_scalars(float* __restrict__ out_scalars) {
    __shared__ double red[256];
    int tid = threadIdx.x;
    double s = 0.0;
    for (int j = tid; j < N_CODE; j += 256) {
        int c = g_counts[j];
        if (c > 0) {
            double p = (double)c / (double)N_TOK;
            s += p * log(p);
        }
    }
    red[tid] = s;
    __syncthreads();
    #pragma unroll
    for (int st = 128; st; st >>= 1) {
        if (tid < st) red[tid] += red[tid + st];
        __syncthreads();
    }
    if (tid == 0) {
        double loss = 1.25 * g_mse / (double)((size_t)N_TOK * CDIM);
        out_scalars[0] = (float)loss;
        out_scalars[1] = (float)exp(-red[0]);
    }
}

// ============================================================
extern "C" void kernel_launch(void* const* d_in, const int* in_sizes, int n_in,
                              void* d_out, int out_size) {
    const float* z   = (const float*)d_in[0];
    const float* emb = (const float*)d_in[1];
    float* out = (float*)d_out;

    int has_extra = (out_size >= (int)OUT_TOTAL) ? 1 : 0;

    cudaFuncSetAttribute(k_passA, cudaFuncAttributeMaxDynamicSharedMemorySize, SM_TOTAL);

    k_prep<<<N_CODE / 8, 256>>>(emb);
    k_transpose<<<1024, 256>>>(z);
    k_passA<<<N_TOK / 128, NTHREADS, SM_TOTAL>>>();
    k_passB<<<N_TOK / 8, 256>>>(emb, out + OUT_IDX, has_extra);
    k_output<<<1024, 256>>>(z, emb, out);
    if (has_extra) k_scalars<<<1, 256>>>(out + OUT_LOSS);
}